// round 16
// baseline (speedup 1.0000x reference)
#include <cuda_runtime.h>
#include <math.h>

// x: [2048, 512, 7, 7] fp32. Each 2-CTA cluster handles one sample;
// CTA rank r owns channels [256r, 256r+256).
#define NCH      512
#define HW       49
#define SLAB     (NCH * HW)        // 25088 floats / sample
#define NTHREADS 256
#define NWARPS   (NTHREADS / 32)   // 8
#define HALF_CH  256
#define CH_PER_W (HALF_CH / NWARPS) // 32 channels per warp
#define HALF_F   (HALF_CH * HW)    // 12544 floats (49KB)
#define HALF_F4  (HALF_F / 4)      // 3136 float4
#define EPS      1e-5f

// HALF_F4 = 3136 = 12*256 + 64
#define FULL_BATCHES 3
#define REM_THREADS  64

__device__ __forceinline__ unsigned smem_u32(const void* p) {
    unsigned a;
    asm("{ .reg .u64 t; cvta.to.shared.u64 t, %1; cvt.u32.u64 %0, t; }"
        : "=r"(a) : "l"(p));
    return a;
}

__global__ __launch_bounds__(NTHREADS, 8) __cluster_dims__(2, 1, 1)
void ModelNew_25056839205377_kernel(const float* __restrict__ x,
                                    float* __restrict__ out)
{
    __shared__ float  ch[HALF_CH + 1];  // own-half gates; +1 slack
    __shared__ float  red[16];          // 8 sums, 8 sumsqs
    __shared__ float2 part;             // own-half (sum, sumsq) for peer

    const int tid  = threadIdx.x;
    const int warp = tid >> 5;
    const int lane = tid & 31;

    unsigned rank;
    asm("mov.u32 %0, %%cluster_ctarank;" : "=r"(rank));
    const int sample = blockIdx.x >> 1;
    const size_t base = (size_t)sample * SLAB + (size_t)rank * HALF_F;
    const float* __restrict__ xp = x + base;

    // ---- Phase 1: y[c] spatial means for own 256 channels ----
    #pragma unroll 8
    for (int k = 0; k < CH_PER_W; ++k) {
        const int c = warp * CH_PER_W + k;      // local channel 0..255
        const float* p = xp + c * HW;
        float s = p[lane] + ((lane < HW - 32) ? p[32 + lane] : 0.0f);
        #pragma unroll
        for (int o = 16; o > 0; o >>= 1)
            s += __shfl_xor_sync(0xffffffffu, s, o);
        if (lane == 0) ch[c] = s * (1.0f / HW);
    }
    __syncwarp();                       // warp reads back only its own ch[]

    // ---- Phase 2: own-half partial (sum, sumsq) ----
    const float y = ch[tid];
    float ys = y, y2 = y * y;
    #pragma unroll
    for (int o = 16; o > 0; o >>= 1) {
        ys += __shfl_xor_sync(0xffffffffu, ys, o);
        y2 += __shfl_xor_sync(0xffffffffu, y2, o);
    }
    if (lane == 0) { red[warp] = ys; red[8 + warp] = y2; }
    __syncthreads();

    // redundant reduce in every warp
    float s1 = (lane < 8) ? red[lane]     : 0.0f;
    float s2 = (lane < 8) ? red[8 + lane] : 0.0f;
    #pragma unroll
    for (int o = 4; o > 0; o >>= 1) {
        s1 += __shfl_xor_sync(0xffffffffu, s1, o);
        s2 += __shfl_xor_sync(0xffffffffu, s2, o);
    }
    s1 = __shfl_sync(0xffffffffu, s1, 0);
    s2 = __shfl_sync(0xffffffffu, s2, 0);

    if (tid == 0) part = make_float2(s1, s2);   // publish own half

    // ---- cluster exchange: release own partial, acquire peer's ----
    asm volatile("barrier.cluster.arrive.aligned;" ::: "memory");
    asm volatile("barrier.cluster.wait.aligned;"   ::: "memory");

    float p1, p2;
    if (lane == 0) {
        unsigned a = smem_u32(&part), pa;
        const unsigned peer = rank ^ 1u;
        asm("mapa.shared::cluster.u32 %0, %1, %2;" : "=r"(pa) : "r"(a), "r"(peer));
        unsigned long long v;
        asm volatile("ld.acquire.cluster.shared::cluster.b64 %0, [%1];"
                     : "=l"(v) : "r"(pa) : "memory");
        p1 = __uint_as_float((unsigned)(v & 0xffffffffu));
        p2 = __uint_as_float((unsigned)(v >> 32));
    }
    p1 = __shfl_sync(0xffffffffu, p1, 0);
    p2 = __shfl_sync(0xffffffffu, p2, 0);

    // ---- Phase 3: full-sample stats + gates for own channels ----
    {
        const float t1  = s1 + p1;
        const float t2  = s2 + p2;
        const float m   = t1 * (1.0f / NCH);
        const float mx2 = t2 * (1.0f / NCH);
        const float var = fmaxf(mx2 - m * m, 0.0f);
        const float inv = rsqrtf(var + EPS);
        const float z   = (y - m) * inv;
        ch[tid] = __expf(-z * z);       // C_PARAM=2 -> exp(-z^2)
    }
    if (tid == 0) ch[HALF_CH] = 0.0f;
    __syncthreads();

    // ---- Phase 4: stream own half: L2-hit re-read, gate, store ----
    const float4* __restrict__ x4 = (const float4*)xp;
    float4* __restrict__ o4 = (float4*)(out + base);

    #pragma unroll
    for (int b = 0; b < FULL_BATCHES; ++b) {
        const int i0 = tid + (4 * b) * NTHREADS;
        float4 v0 = __ldcs(x4 + i0 + 0 * NTHREADS);
        float4 v1 = __ldcs(x4 + i0 + 1 * NTHREADS);
        float4 v2 = __ldcs(x4 + i0 + 2 * NTHREADS);
        float4 v3 = __ldcs(x4 + i0 + 3 * NTHREADS);
        #pragma unroll
        for (int k = 0; k < 4; ++k) {
            float4& v = (k == 0) ? v0 : (k == 1) ? v1 : (k == 2) ? v2 : v3;
            const int e = (i0 + k * NTHREADS) * 4;
            const int c = e / HW;               // local channel
            const int r = e - c * HW;           // 0..48
            const float g0 = ch[c];
            const float gn = ch[c + 1];
            v.x *= g0;
            v.y *= (r < 48) ? g0 : gn;
            v.z *= (r < 47) ? g0 : gn;
            v.w *= (r < 46) ? g0 : gn;
            __stcs(o4 + i0 + k * NTHREADS, v);
        }
    }
    // remainder: 3136 - 12*256 = 64 float4s
    if (tid < REM_THREADS) {
        const int i = tid + 12 * NTHREADS;
        float4 v = __ldcs(x4 + i);
        const int e = i * 4;
        const int c = e / HW;
        const int r = e - c * HW;
        const float g0 = ch[c];
        const float gn = ch[c + 1];
        v.x *= g0;
        v.y *= (r < 48) ? g0 : gn;
        v.z *= (r < 47) ? g0 : gn;
        v.w *= (r < 46) ? g0 : gn;
        __stcs(o4 + i, v);
    }

    // ---- trailing cluster barrier: no CTA exits while a peer's DSMEM
    //      access (the partial-stats read) could still be in flight ----
    asm volatile("barrier.cluster.arrive.aligned;" ::: "memory");
    asm volatile("barrier.cluster.wait.aligned;"   ::: "memory");
}

extern "C" void kernel_launch(void* const* d_in, const int* in_sizes, int n_in,
                              void* d_out, int out_size)
{
    const float* x = (const float*)d_in[0];
    float* out = (float*)d_out;
    const int nsamples = in_sizes[0] / SLAB;   // 2048
    ModelNew_25056839205377_kernel<<<nsamples * 2, NTHREADS>>>(x, out);
}